// round 9
// baseline (speedup 1.0000x reference)
#include <cuda_runtime.h>
#include <cstdint>

#define TASKS    128
#define NSAMP    2048
#define INDIM    256
#define OUTDIM   256
#define GRP      8            // samples per work item
#define MAXITEMS 384          // sum ceil(cnt/8) <= 2048/8 + 128
#define K2_GRID  (2 * MAXITEMS)

__device__ unsigned short g_slist[NSAMP];
__device__ int2 g_items[MAXITEMS];   // x = base | (scount<<16), y = task
__device__ int g_nitems;

__device__ __forceinline__ unsigned smem_u32(const void* p) {
    unsigned r;
    asm("{ .reg .u64 t; cvta.to.shared.u64 t, %1; cvt.u32.u64 %0, t; }" : "=r"(r) : "l"(p));
    return r;
}
__device__ __forceinline__ unsigned long long dup2(float f) {
    unsigned long long d; unsigned u = __float_as_uint(f);
    asm("mov.b64 %0, {%1, %1};" : "=l"(d) : "r"(u));
    return d;
}

// ---------------- K1: 1024-thread histogram + warp-shfl scans + worklist ----------------
__global__ __launch_bounds__(1024) void k1_scan(const void* __restrict__ TIDS)
{
    __shared__ int cnts[TASKS], cursor[TASKS];
    __shared__ int soff[TASKS + 1], ioff[TASKS];
    __shared__ unsigned orv;

    const int tid = threadIdx.x;
    if (tid < TASKS) { cnts[tid] = 0; cursor[tid] = 0; }
    if (tid == 0) orv = 0;
    __syncthreads();

    const unsigned* w32 = (const unsigned*)TIDS;
    // dtype detect: int64 iff hi 32-bit words are all zero (256 samples is plenty:
    // for int32 data those words are ids, P(all zero) ~ (1/128)^256).
    if (tid < 256) atomicOr(&orv, w32[2 * tid + 1]);
    __syncthreads();
    const int shift = (orv == 0) ? 1 : 0;

    int id0, id1;
    {
        const int n0 = tid, n1 = tid + 1024;
        id0 = (int)w32[(unsigned)n0 << shift];
        id1 = (int)w32[(unsigned)n1 << shift];
        atomicAdd(&cnts[id0], 1);
        atomicAdd(&cnts[id1], 1);
    }
    __syncthreads();

    if (tid < 32) {                       // warp 0: both prefix scans via shfl
        int c[4], pc[4], pi[4];
        int sc = 0, si = 0;
        #pragma unroll
        for (int j = 0; j < 4; ++j) {
            c[j] = cnts[tid * 4 + j];
            pc[j] = sc; sc += c[j];
            pi[j] = si; si += (c[j] + GRP - 1) >> 3;
        }
        int vc = sc, vi = si;
        #pragma unroll
        for (int d = 1; d < 32; d <<= 1) {
            int uc = __shfl_up_sync(0xffffffffu, vc, d);
            int ui = __shfl_up_sync(0xffffffffu, vi, d);
            if (tid >= d) { vc += uc; vi += ui; }
        }
        const int ec = vc - sc, ei = vi - si;
        #pragma unroll
        for (int j = 0; j < 4; ++j) {
            soff[tid * 4 + j] = ec + pc[j];
            ioff[tid * 4 + j] = ei + pi[j];
        }
        if (tid == 31) { soff[TASKS] = ec + sc; g_nitems = ei + si; }
    }
    __syncthreads();

    if (tid < TASKS) {
        const int b = soff[tid], cnt = soff[tid + 1] - b, io = ioff[tid];
        for (int g = 0; g * GRP < cnt; ++g) {
            int rem = cnt - g * GRP; if (rem > GRP) rem = GRP;
            g_items[io + g] = make_int2((b + GRP * g) | (rem << 16), tid);
        }
    }
    {
        int p0 = atomicAdd(&cursor[id0], 1);
        g_slist[soff[id0] + p0] = (unsigned short)tid;
        int p1 = atomicAdd(&cursor[id1], 1);
        g_slist[soff[id1] + p1] = (unsigned short)(tid + 1024);
    }   // in-task order irrelevant: per-sample i-order is fixed -> deterministic output
}

// ---------------- K2: CTA = (8 samples x 128 cols); thread = 1 col x 8 samples ----------------
// x rows broadcast-LDS with 4 buffers / 2-stage lookahead; W scalar with 16-deep prefetch.
__device__ __forceinline__ void stage(float& w, const float* __restrict__ pf, bool pm,
                                      unsigned long long (&xu)[4], unsigned long long (&xl)[4],
                                      unsigned la, unsigned long long (&acc)[4])
{
    const unsigned long long wd = dup2(w);
    if (pm) w = __ldg(pf);                           // prefetch W for i+16
    asm("ld.shared.v2.b64 {%0,%1},[%2];" : "=l"(xl[0]), "=l"(xl[1]) : "r"(la));
    asm("ld.shared.v2.b64 {%0,%1},[%2];" : "=l"(xl[2]), "=l"(xl[3]) : "r"(la + 16));
    asm("fma.rn.f32x2 %0, %1, %2, %0;" : "+l"(acc[0]) : "l"(xu[0]), "l"(wd));
    asm("fma.rn.f32x2 %0, %1, %2, %0;" : "+l"(acc[1]) : "l"(xu[1]), "l"(wd));
    asm("fma.rn.f32x2 %0, %1, %2, %0;" : "+l"(acc[2]) : "l"(xu[2]), "l"(wd));
    asm("fma.rn.f32x2 %0, %1, %2, %0;" : "+l"(acc[3]) : "l"(xu[3]), "l"(wd));
}

__global__ __launch_bounds__(128) void k2_gemm(const float* __restrict__ X,
                                               const float* __restrict__ W,
                                               float* __restrict__ OUT)
{
    __shared__ __align__(16) float xt[INDIM * GRP + 2 * GRP];  // 8KB + 64B pad (2-row overread)
    __shared__ unsigned short sl[GRP];

    const int tid  = threadIdx.x;
    const int item = blockIdx.x >> 1;
    const int half = blockIdx.x & 1;
    if (item >= g_nitems) return;

    const int2 it = g_items[item];
    const int base = it.x & 0xffff, scount = it.x >> 16, task = it.y;

    if (tid < GRP) sl[tid] = (tid < scount) ? g_slist[base + tid] : (unsigned short)0;

    {   // transposed tile fill: thread -> (s = tid&7, q = tid>>3 in 0..15), 4 LDG.128 each
        const int s = tid & 7, q = tid >> 3;
        const bool valid = (s < scount);
        const float4* row = (const float4*)(X +
            (valid ? (unsigned)g_slist[base + s] * INDIM : 0u));
        #pragma unroll
        for (int k = 0; k < 4; ++k) {
            const int iv = q + 16 * k;
            float4 v;
            if (valid) v = __ldg(row + iv);
            else       v = make_float4(0.f, 0.f, 0.f, 0.f);
            const int i = iv * 4;
            xt[(i + 0) * GRP + s] = v.x;
            xt[(i + 1) * GRP + s] = v.y;
            xt[(i + 2) * GRP + s] = v.z;
            xt[(i + 3) * GRP + s] = v.w;
        }
    }
    __syncthreads();

    const int o = half * 128 + tid;
    const float* Wb = W + (size_t)task * INDIM * OUTDIM + o;   // + i*256 per row
    const unsigned xb = smem_u32(xt);

    unsigned long long acc[4];
    acc[0] = acc[1] = acc[2] = acc[3] = 0ull;

    float wA[8], wB[8];
    #pragma unroll
    for (int j = 0; j < 8; ++j) {
        wA[j] = __ldg(Wb + (size_t)j * OUTDIM);
        wB[j] = __ldg(Wb + (size_t)(8 + j) * OUTDIM);
    }

    // x pipeline: 4 buffers, 2-stage lookahead. X0=row0, X1=row1 preloaded.
    unsigned long long X0[4], X1[4], X2[4], X3[4];
    asm("ld.shared.v2.b64 {%0,%1},[%2];" : "=l"(X0[0]), "=l"(X0[1]) : "r"(xb));
    asm("ld.shared.v2.b64 {%0,%1},[%2];" : "=l"(X0[2]), "=l"(X0[3]) : "r"(xb + 16));
    asm("ld.shared.v2.b64 {%0,%1},[%2];" : "=l"(X1[0]), "=l"(X1[1]) : "r"(xb + 32));
    asm("ld.shared.v2.b64 {%0,%1},[%2];" : "=l"(X1[2]), "=l"(X1[3]) : "r"(xb + 48));

    #pragma unroll 1
    for (int m = 0; m < 16; ++m) {                 // 16 i-values per iteration
        const bool pm = (m < 15);
        const unsigned ib = xb + (unsigned)m * (16 * 32);        // row i = 16m, 32B/row
        const float* Wp = Wb + (size_t)(16 * m + 16) * OUTDIM;   // prefetch base (i+16)
        // stage j: compute row 16m+j from X[j%4], load row 16m+j+2 into X[(j+2)%4]
        stage(wA[0], Wp + 0  * OUTDIM, pm, X0, X2, ib + 2  * 32, acc);
        stage(wA[1], Wp + 1  * OUTDIM, pm, X1, X3, ib + 3  * 32, acc);
        stage(wA[2], Wp + 2  * OUTDIM, pm, X2, X0, ib + 4  * 32, acc);
        stage(wA[3], Wp + 3  * OUTDIM, pm, X3, X1, ib + 5  * 32, acc);
        stage(wA[4], Wp + 4  * OUTDIM, pm, X0, X2, ib + 6  * 32, acc);
        stage(wA[5], Wp + 5  * OUTDIM, pm, X1, X3, ib + 7  * 32, acc);
        stage(wA[6], Wp + 6  * OUTDIM, pm, X2, X0, ib + 8  * 32, acc);
        stage(wA[7], Wp + 7  * OUTDIM, pm, X3, X1, ib + 9  * 32, acc);
        stage(wB[0], Wp + 8  * OUTDIM, pm, X0, X2, ib + 10 * 32, acc);
        stage(wB[1], Wp + 9  * OUTDIM, pm, X1, X3, ib + 11 * 32, acc);
        stage(wB[2], Wp + 10 * OUTDIM, pm, X2, X0, ib + 12 * 32, acc);
        stage(wB[3], Wp + 11 * OUTDIM, pm, X3, X1, ib + 13 * 32, acc);
        stage(wB[4], Wp + 12 * OUTDIM, pm, X0, X2, ib + 14 * 32, acc);
        stage(wB[5], Wp + 13 * OUTDIM, pm, X1, X3, ib + 15 * 32, acc);
        stage(wB[6], Wp + 14 * OUTDIM, pm, X2, X0, ib + 16 * 32, acc);
        stage(wB[7], Wp + 15 * OUTDIM, pm, X3, X1, ib + 17 * 32, acc); // m=15: reads 64B pad
    }

    #pragma unroll
    for (int p = 0; p < 4; ++p) {
        unsigned lo, hi;
        asm("mov.b64 {%0,%1},%2;" : "=r"(lo), "=r"(hi) : "l"(acc[p]));
        const int s0 = 2 * p, s1 = 2 * p + 1;
        if (s0 < scount) OUT[(size_t)sl[s0] * OUTDIM + o] = __uint_as_float(lo);
        if (s1 < scount) OUT[(size_t)sl[s1] * OUTDIM + o] = __uint_as_float(hi);
    }
}

extern "C" void kernel_launch(void* const* d_in, const int* in_sizes, int n_in,
                              void* d_out, int out_size)
{
    const float* X    = (const float*)d_in[0];
    const void*  TIDS = d_in[1];
    const float* W    = (const float*)d_in[2];
    float*       OUT  = (float*)d_out;

    k1_scan<<<1, 1024>>>(TIDS);
    k2_gemm<<<K2_GRID, 128>>>(X, W, OUT);
}